// round 5
// baseline (speedup 1.0000x reference)
#include <cuda_runtime.h>
#include <cuda_bf16.h>

// 8x8 blockwise DCT with output transpose:
//   OUT[v][u] = sum_{k,l} D[u,k] * X[k,l] * D[v,l]
// x: (32, 3, 512, 512) fp32   dct_basis: (8,8) fp32
//
// R4 structure (CTA per 8x512 strip, coalesced smem staging, 4 thr/block)
// + XOR swizzle on the strip's smem columns so compute-phase LDS.128 is
// bank-conflict-free (was 2-way): logical col c stored at c ^ ((c&32)>>3).

#define IMG_DIM      512
#define NIMG         (32 * 3)
#define STRIPS       (NIMG * (IMG_DIM / 8))    // 6144
#define STRIP_FLOATS (8 * IMG_DIM)             // 4096
#define TPB          256

__device__ __forceinline__ int swz_col(int col) {
    return col ^ ((col & 32) >> 3);
}

__global__ __launch_bounds__(TPB, 6) void dct_blocks_kernel(
    const float* __restrict__ x,
    const float* __restrict__ dct,
    float* __restrict__ out)
{
    __shared__ float S[STRIP_FLOATS];   // 8x512 strip, columns XOR-swizzled
    __shared__ float Ds[64];            // D row-major:  Ds[v*8+l] = D[v][l]
    __shared__ float Dt[64];            // D transposed: Dt[k*8+u] = D[u][k]

    if (threadIdx.x < 64) {
        float val = dct[threadIdx.x];
        Ds[threadIdx.x] = val;
        int u = threadIdx.x >> 3;
        int k = threadIdx.x & 7;
        Dt[k * 8 + u] = val;
    }

    size_t base = (size_t)blockIdx.x * STRIP_FLOATS;
    const float4* src4 = (const float4*)(x + base);
    float*        dst  = out + base;

    // Phase 1: coalesced strip load (each 128B line fetched exactly once),
    // stored to swizzled smem columns. STS stays at its 4-phase floor.
    #pragma unroll
    for (int i = 0; i < 4; ++i) {
        int idx = threadIdx.x + i * TPB;     // float4 index 0..1023
        float4 v = src4[idx];
        int k   = idx >> 7;                  // row (128 float4 per row)
        int col = (idx & 127) << 2;          // logical float column
        *(float4*)(S + k * IMG_DIM + swz_col(col)) = v;
    }
    __syncthreads();

    // Phase 2: thread (bx, q) computes output columns uo..uo+1 of block bx.
    int q  = threadIdx.x & 3;
    int bx = threadIdx.x >> 2;
    int uo = q * 2;

    // Swizzled locations of this block's lo (cols 0-3) and hi (cols 4-7) chunks.
    int swz   = bx & 4;                  // 0 or 4
    int loCol = bx * 8 + swz;            // where logical cols [0,4) live
    int hiCol = bx * 8 + (4 - swz);      // where logical cols [4,8) live

    // Stage 1: t[u2][l] = sum_k D[uo+u2, k] * X[k, l]
    float t0[8], t1[8];
    #pragma unroll
    for (int l = 0; l < 8; ++l) { t0[l] = 0.0f; t1[l] = 0.0f; }

    #pragma unroll
    for (int k = 0; k < 8; ++k) {
        const float* row = S + k * IMG_DIM;
        float4 a = *(const float4*)(row + loCol);   // logical cols 0-3
        float4 b = *(const float4*)(row + hiCol);   // logical cols 4-7
        float xr[8] = {a.x, a.y, a.z, a.w, b.x, b.y, b.z, b.w};
        float2 dk = *(const float2*)(Dt + k * 8 + uo);  // D[uo..uo+1][k]
        #pragma unroll
        for (int l = 0; l < 8; ++l) {
            t0[l] = fmaf(dk.x, xr[l], t0[l]);
            t1[l] = fmaf(dk.y, xr[l], t1[l]);
        }
    }

    // Stage 2: OUT[v][uo+u2] = sum_l t[u2][l] * D[v, l]; coalesced float2 store.
    #pragma unroll
    for (int v = 0; v < 8; ++v) {
        float4 d0 = *(const float4*)(Ds + v * 8);
        float4 d1 = *(const float4*)(Ds + v * 8 + 4);
        float dv[8] = {d0.x, d0.y, d0.z, d0.w, d1.x, d1.y, d1.z, d1.w};
        float s0 = 0.0f, s1 = 0.0f;
        #pragma unroll
        for (int l = 0; l < 8; ++l) {
            s0 = fmaf(t0[l], dv[l], s0);
            s1 = fmaf(t1[l], dv[l], s1);
        }
        *(float2*)(dst + (size_t)v * IMG_DIM + bx * 8 + uo) = make_float2(s0, s1);
    }
}

extern "C" void kernel_launch(void* const* d_in, const int* in_sizes, int n_in,
                              void* d_out, int out_size)
{
    const float* x   = (const float*)d_in[0];
    const float* dct = (const float*)d_in[1];
    float*       out = (float*)d_out;

    dct_blocks_kernel<<<STRIPS, TPB>>>(x, dct, out);
}

// round 6
// speedup vs baseline: 1.1267x; 1.1267x over previous
#include <cuda_runtime.h>
#include <cuda_bf16.h>

// 8x8 blockwise DCT with output transpose:
//   OUT[v][u] = sum_{k,l} D[u,k] * X[k,l] * D[v,l]
// x: (32, 3, 512, 512) fp32   dct_basis: (8,8) fp32
//
// CTA per 8x512 strip. Smem strip stored as TWO 16B-chunk planes:
//   plane0[k][bx] = block bx cols 0-3 of row k, plane1[k][bx] = cols 4-7.
// Compute-phase LDS.128 then reads 8 chunks at 16B stride = 128B contiguous
// -> 1 conflict-free phase (R4's interleaved layout cost 2). Addressing is
// base+immediate only (no XOR ALU like the failed R5).

#define IMG_DIM      512
#define NIMG         (32 * 3)
#define STRIPS       (NIMG * (IMG_DIM / 8))    // 6144
#define STRIP_FLOATS (8 * IMG_DIM)             // 4096
#define PLANE        2048                      // floats per plane (8 rows x 64 chunks x 4)
#define TPB          256

__global__ __launch_bounds__(TPB, 6) void dct_blocks_kernel(
    const float* __restrict__ x,
    const float* __restrict__ dct,
    float* __restrict__ out)
{
    __shared__ float S[STRIP_FLOATS];   // [2 planes][8 rows][64 chunks][4]
    __shared__ float Ds[64];            // D row-major:  Ds[v*8+l] = D[v][l]
    __shared__ float Dt[64];            // D transposed: Dt[k*8+u] = D[u][k]

    if (threadIdx.x < 64) {
        float val = dct[threadIdx.x];
        Ds[threadIdx.x] = val;
        int u = threadIdx.x >> 3;
        int k = threadIdx.x & 7;
        Dt[k * 8 + u] = val;
    }

    size_t base = (size_t)blockIdx.x * STRIP_FLOATS;
    const float4* src4 = (const float4*)(x + base);
    float*        dst  = out + base;

    // Phase 1: coalesced strip load (each 128B DRAM line fetched exactly once),
    // scattered into the two chunk planes. STS: 512B/instr = 4-phase floor.
    #pragma unroll
    for (int i = 0; i < 4; ++i) {
        int idx = threadIdx.x + i * TPB;     // float4 index 0..1023
        float4 v = src4[idx];
        int k = idx >> 7;                    // strip row
        int c = idx & 127;                   // chunk within row
        int b = c >> 1;                      // block index
        int p = c & 1;                       // lo/hi half of the block row
        *(float4*)(S + p * PLANE + k * 256 + b * 4) = v;
    }
    __syncthreads();

    // Phase 2: thread (bx, q) computes output columns uo..uo+1 of block bx.
    int q  = threadIdx.x & 3;
    int bx = threadIdx.x >> 2;
    int uo = q * 2;

    const float* Slo = S + bx * 4;           // plane 0: cols 0-3 of block bx
    const float* Shi = S + PLANE + bx * 4;   // plane 1: cols 4-7

    // Stage 1: t[u2][l] = sum_k D[uo+u2, k] * X[k, l]
    float t0[8], t1[8];
    #pragma unroll
    for (int l = 0; l < 8; ++l) { t0[l] = 0.0f; t1[l] = 0.0f; }

    #pragma unroll
    for (int k = 0; k < 8; ++k) {
        float4 a = *(const float4*)(Slo + k * 256);   // cols 0-3, 1-phase LDS
        float4 b = *(const float4*)(Shi + k * 256);   // cols 4-7, 1-phase LDS
        float xr[8] = {a.x, a.y, a.z, a.w, b.x, b.y, b.z, b.w};
        float2 dk = *(const float2*)(Dt + k * 8 + uo);  // D[uo..uo+1][k]
        #pragma unroll
        for (int l = 0; l < 8; ++l) {
            t0[l] = fmaf(dk.x, xr[l], t0[l]);
            t1[l] = fmaf(dk.y, xr[l], t1[l]);
        }
    }

    // Stage 2: OUT[v][uo+u2] = sum_l t[u2][l] * D[v, l]; coalesced float2 store.
    #pragma unroll
    for (int v = 0; v < 8; ++v) {
        float4 d0 = *(const float4*)(Ds + v * 8);
        float4 d1 = *(const float4*)(Ds + v * 8 + 4);
        float dv[8] = {d0.x, d0.y, d0.z, d0.w, d1.x, d1.y, d1.z, d1.w};
        float s0 = 0.0f, s1 = 0.0f;
        #pragma unroll
        for (int l = 0; l < 8; ++l) {
            s0 = fmaf(t0[l], dv[l], s0);
            s1 = fmaf(t1[l], dv[l], s1);
        }
        *(float2*)(dst + (size_t)v * IMG_DIM + bx * 8 + uo) = make_float2(s0, s1);
    }
}

extern "C" void kernel_launch(void* const* d_in, const int* in_sizes, int n_in,
                              void* d_out, int out_size)
{
    const float* x   = (const float*)d_in[0];
    const float* dct = (const float*)d_in[1];
    float*       out = (float*)d_out;

    dct_blocks_kernel<<<STRIPS, TPB>>>(x, dct, out);
}